// round 1
// baseline (speedup 1.0000x reference)
#include <cuda_runtime.h>
#include <math.h>

// Problem constants (shapes fixed by the dataset): x (4,64,128,128), k (4,64,25,25),
// alpha (1,64,1,1), sf = 2.  Output (4,64,256,256) fp32.
#define NPLANES 256          // B*C
#define NCH 64

// ---------------------------------------------------------------------------
// Scratch (allocation-free: __device__ globals)
// ---------------------------------------------------------------------------
__device__ float2 g_SA[NPLANES * 256 * 256];   // 128 MB
__device__ float2 g_SB[NPLANES * 256 * 256];   // 128 MB
__device__ float2 g_SC[NPLANES * 128 * 128];   // 32  MB  (Fx = fft2_128(x)^T)
__device__ float2 g_tw[256];                   // e^{-2*pi*i * t / 256}

__device__ __forceinline__ float2 cmulf(float2 a, float2 b) {
    return make_float2(a.x * b.x - a.y * b.y, a.x * b.y + a.y * b.x);
}

__global__ void k_twinit() {
    int t = threadIdx.x;
    float s, c;
    sincospif(-(float)t * (1.0f / 128.0f), &s, &c);   // -2*pi*t/256
    g_tw[t] = make_float2(c, s);
}

// ---------------------------------------------------------------------------
// Stockham radix-2 FFT of length N in shared memory.
// b0/b1: ping-pong buffers of N complex each. tid in [0, N/2).
// Caller must __syncthreads() after the cooperative load, before calling.
// Returns pointer to the buffer holding the result.
// ---------------------------------------------------------------------------
template <int N, bool INV>
__device__ __forceinline__ float2* fft_row(float2* b0, float2* b1, int tid) {
    float2* src = b0;
    float2* dst = b1;
    int Ns = 1;
    const int LOG = (N == 256) ? 8 : 7;
#pragma unroll
    for (int st = 0; st < LOG; ++st) {
        int jmod = tid & (Ns - 1);
        float2 a = src[tid];
        float2 b = src[tid + N / 2];
        float2 w = g_tw[jmod * (128 / Ns)];   // e^{-2 pi i * jmod/(2*Ns)}
        float wy = INV ? -w.y : w.y;
        float2 bw = make_float2(b.x * w.x - b.y * wy, b.x * wy + b.y * w.x);
        int idxD = ((tid - jmod) << 1) | jmod;   // (tid/Ns)*2Ns + jmod
        dst[idxD]      = make_float2(a.x + bw.x, a.y + bw.y);
        dst[idxD + Ns] = make_float2(a.x - bw.x, a.y - bw.y);
        __syncthreads();
        float2* t = src; src = dst; dst = t;
        Ns <<= 1;
    }
    return src;
}

// ---------------------------------------------------------------------------
// Pass 1 of FB: row FFT (N=256) of padded + rolled PSF (p2o fused into load).
// otf[i][j] = psf[(i+12)&255][(j+12)&255] if both < 25 else 0   (kh//2 = 12)
// 231/256 rows are identically zero: whole-zero blocks just write zeros.
// Writes g_SA.
// ---------------------------------------------------------------------------
__global__ void k_fb_pass1(const float* __restrict__ psf) {
    const int N = 256, HALF = 128, ROWS = 4;
    __shared__ float2 sm[ROWS][2 * N];
    int tid = threadIdx.x;                 // 0..127
    int ry  = threadIdx.y;                 // 0..3
    int gr  = blockIdx.x * ROWS + ry;      // global row
    int p = gr >> 8;
    int i = gr & 255;

    int i0 = (blockIdx.x * ROWS) & 255;    // block never straddles a plane
    if (i0 >= 13 && i0 + ROWS - 1 <= 243) {
        // all rows in this block map to r >= 25 -> FFT of zeros is zeros
        float2 z = make_float2(0.f, 0.f);
        g_SA[gr * N + tid] = z;
        g_SA[gr * N + tid + HALF] = z;
        return;
    }

    int r = (i + 12) & 255;
    bool rowok = (r < 25);
    const float* kp = psf + p * 625 + r * 25;

    int c0 = (tid + 12) & 255;
    int c1 = (tid + HALF + 12) & 255;
    float v0 = (rowok && c0 < 25) ? kp[c0] : 0.f;
    float v1 = (rowok && c1 < 25) ? kp[c1] : 0.f;
    sm[ry][tid]        = make_float2(v0, 0.f);
    sm[ry][tid + HALF] = make_float2(v1, 0.f);
    __syncthreads();

    float2* res = fft_row<256, false>(sm[ry], sm[ry] + N, tid);
    g_SA[gr * N + tid]        = res[tid];
    g_SA[gr * N + tid + HALF] = res[tid + HALF];
}

// ---------------------------------------------------------------------------
// Row FFT of x (N=128, real input). Writes region 0 of g_SB.
// ---------------------------------------------------------------------------
__global__ void k_x_pass1(const float* __restrict__ x) {
    const int N = 128, HALF = 64, ROWS = 8;
    __shared__ float2 sm[ROWS][2 * N];
    int tid = threadIdx.x;                 // 0..63
    int ry  = threadIdx.y;
    int gr  = blockIdx.x * ROWS + ry;      // over NPLANES*128 rows
    const float* xs = x + gr * N;
    sm[ry][tid]        = make_float2(xs[tid], 0.f);
    sm[ry][tid + HALF] = make_float2(xs[tid + HALF], 0.f);
    __syncthreads();
    float2* res = fft_row<128, false>(sm[ry], sm[ry] + N, tid);
    g_SB[gr * N + tid]        = res[tid];
    g_SB[gr * N + tid + HALF] = res[tid + HALF];
}

// ---------------------------------------------------------------------------
// Generic complex row-FFT pass (forward or inverse, with output scale).
// ---------------------------------------------------------------------------
template <int N, int ROWS, bool INV>
__global__ void k_cfft(const float2* __restrict__ src, float2* __restrict__ dst,
                       float scale) {
    __shared__ float2 sm[ROWS][2 * N];
    int tid = threadIdx.x;
    int ry  = threadIdx.y;
    int gr  = blockIdx.x * ROWS + ry;
    const float2* s = src + gr * N;
    sm[ry][tid]         = s[tid];
    sm[ry][tid + N / 2] = s[tid + N / 2];
    __syncthreads();
    float2* res = fft_row<N, INV>(sm[ry], sm[ry] + N, tid);
    float2 o0 = res[tid];
    float2 o1 = res[tid + N / 2];
    dst[gr * N + tid]         = make_float2(o0.x * scale, o0.y * scale);
    dst[gr * N + tid + N / 2] = make_float2(o1.x * scale, o1.y * scale);
}

// ---------------------------------------------------------------------------
// Per-plane tile transpose (N = 128 or 256).
// ---------------------------------------------------------------------------
template <int N>
__global__ void k_transpose(const float2* __restrict__ src, float2* __restrict__ dst) {
    __shared__ float2 tile[32][33];
    int p = blockIdx.z;
    const float2* s = src + p * N * N;
    float2* d = dst + p * N * N;
    int x0 = blockIdx.x * 32, y0 = blockIdx.y * 32;
    int tx = threadIdx.x;
    for (int ty = threadIdx.y; ty < 32; ty += blockDim.y)
        tile[ty][tx] = s[(y0 + ty) * N + x0 + tx];
    __syncthreads();
    for (int ty = threadIdx.y; ty < 32; ty += blockDim.y)
        d[(x0 + ty) * N + y0 + tx] = tile[tx][ty];
}

// ---------------------------------------------------------------------------
// Fully fused mid-section.  Stored arrays are fft2(.)^T (transpose-consistent).
// Each thread owns one quadrant group {(v+128a, u+128b)}:
//   FR_q   = Fx * (conj(FB_q) + be * P(U)*P(V)),  P(t) = 1 + e^{-i pi t/128}
//   FBR    = mean_q(FB_q * FR_q);  invW = mean_q(|FB_q|^2)
//   iw     = FBR / (invW + be)
//   FX_q   = (FR_q - conj(FB_q) * iw) / be
// Reads g_SA (FB) + g_SC (Fx); writes g_SB (FX).
// ---------------------------------------------------------------------------
__global__ void k_mid(const float* __restrict__ alpha) {
    int idx = blockIdx.x * blockDim.x + threadIdx.x;   // NPLANES*128*128 threads
    int u = idx & 127;
    int v = (idx >> 7) & 127;
    int p = idx >> 14;

    float a = alpha[p & (NCH - 1)];
    float be = 1.f / (1.f + expf(9.f - a)) + 1e-3f;    // sigmoid(alpha-9)+eps

    float2 fx = g_SC[(p << 14) + (v << 7) + u];
    int base = p << 16;

    float2 twu0 = g_tw[u],  twu1 = g_tw[u + 128];
    float2 twv0 = g_tw[v],  twv1 = g_tw[v + 128];

    float2 FB[4], FR[4];
    float2 sBR = make_float2(0.f, 0.f);
    float  sW = 0.f;
#pragma unroll
    for (int q = 0; q < 4; ++q) {
        int qa = q >> 1, qb = q & 1;
        int V = v + (qa << 7), U = u + (qb << 7);
        float2 fb = g_SA[base + (V << 8) + U];
        FB[q] = fb;
        float2 tu = qb ? twu1 : twu0;
        float2 tv = qa ? twv1 : twv0;
        float2 pu = make_float2(1.f + tu.x, tu.y);
        float2 pv = make_float2(1.f + tv.x, tv.y);
        float2 P  = cmulf(pu, pv);
        float2 m  = make_float2(fb.x + be * P.x, -fb.y + be * P.y);  // conj(FB)+be*P
        float2 fr = cmulf(fx, m);
        FR[q] = fr;
        sBR.x += fb.x * fr.x - fb.y * fr.y;
        sBR.y += fb.x * fr.y + fb.y * fr.x;
        sW    += fb.x * fb.x + fb.y * fb.y;
    }
    sBR.x *= 0.25f; sBR.y *= 0.25f; sW *= 0.25f;
    float inv = 1.f / (sW + be);
    float2 iw = make_float2(sBR.x * inv, sBR.y * inv);
    float ibe = 1.f / be;
#pragma unroll
    for (int q = 0; q < 4; ++q) {
        int qa = q >> 1, qb = q & 1;
        int V = v + (qa << 7), U = u + (qb << 7);
        // conj(FB)*iw
        float2 t = make_float2(FB[q].x * iw.x + FB[q].y * iw.y,
                               FB[q].x * iw.y - FB[q].y * iw.x);
        g_SB[base + (V << 8) + U] =
            make_float2((FR[q].x - t.x) * ibe, (FR[q].y - t.y) * ibe);
    }
}

// ---------------------------------------------------------------------------
// Final inverse row-FFT pass: writes real part * (1/256) to the output.
// ---------------------------------------------------------------------------
__global__ void k_ifinal(const float2* __restrict__ src, float* __restrict__ out) {
    const int N = 256, HALF = 128, ROWS = 4;
    __shared__ float2 sm[ROWS][2 * N];
    int tid = threadIdx.x;
    int ry  = threadIdx.y;
    int gr  = blockIdx.x * ROWS + ry;
    const float2* s = src + gr * N;
    sm[ry][tid]        = s[tid];
    sm[ry][tid + HALF] = s[tid + HALF];
    __syncthreads();
    float2* res = fft_row<256, true>(sm[ry], sm[ry] + N, tid);
    const float sc = 1.0f / 256.0f;
    out[gr * N + tid]        = res[tid].x * sc;
    out[gr * N + tid + HALF] = res[tid + HALF].x * sc;
}

// ---------------------------------------------------------------------------
extern "C" void kernel_launch(void* const* d_in, const int* in_sizes, int n_in,
                              void* d_out, int out_size) {
    const float* x     = (const float*)d_in[0];   // (4,64,128,128)
    const float* psf   = (const float*)d_in[1];   // (4,64,25,25)
    const float* alpha = (const float*)d_in[2];   // (1,64,1,1)
    // d_in[3] = sf (always 2)
    float* out = (float*)d_out;                   // (4,64,256,256)

    float2 *SA, *SB, *SC;
    cudaGetSymbolAddress((void**)&SA, g_SA);
    cudaGetSymbolAddress((void**)&SB, g_SB);
    cudaGetSymbolAddress((void**)&SC, g_SC);

    k_twinit<<<1, 256>>>();

    // FB = fft2(p2o(k))^T  -> SA
    k_fb_pass1<<<NPLANES * 256 / 4, dim3(128, 4)>>>(psf);
    k_transpose<256><<<dim3(8, 8, NPLANES), dim3(32, 8)>>>(SA, SB);
    k_cfft<256, 4, false><<<NPLANES * 256 / 4, dim3(128, 4)>>>(SB, SA, 1.0f);

    // Fx = fft2_128(x)^T -> SC   (SB regions 0 and 1 as temps)
    k_x_pass1<<<NPLANES * 128 / 8, dim3(64, 8)>>>(x);
    k_transpose<128><<<dim3(4, 4, NPLANES), dim3(32, 8)>>>(SB, SB + NPLANES * 128 * 128);
    k_cfft<128, 8, false><<<NPLANES * 128 / 8, dim3(64, 8)>>>(SB + NPLANES * 128 * 128, SC, 1.0f);

    // Fused frequency-domain solve -> SB holds FX^T
    k_mid<<<NPLANES * 128 * 128 / 256, 256>>>(alpha);

    // out = real(ifft2(FX))
    k_cfft<256, 4, true><<<NPLANES * 256 / 4, dim3(128, 4)>>>(SB, SA, 1.0f / 256.0f);
    k_transpose<256><<<dim3(8, 8, NPLANES), dim3(32, 8)>>>(SA, SB);
    k_ifinal<<<NPLANES * 256 / 4, dim3(128, 4)>>>(SB, out);
}

// round 2
// speedup vs baseline: 1.7588x; 1.7588x over previous
#include <cuda_runtime.h>
#include <math.h>

// Shapes fixed: x (4,64,128,128), k (4,64,25,25), alpha (1,64,1,1), sf=2.
// Output (4,64,256,256) fp32.
#define NPLANES 256
#define NCH 64

// ---------------------------------------------------------------------------
// Scratch (__device__ globals; allocation-free)
// ---------------------------------------------------------------------------
__device__ float2 g_SA[NPLANES * 256 * 256];   // 128 MB : FB^T, temps
__device__ float2 g_SB[NPLANES * 256 * 256];   // 128 MB : FX^T, temps
__device__ float2 g_SC[NPLANES * 128 * 128];   // 32  MB : Rf, then Fx^T
__device__ float2 g_tw[256];                   // e^{-2*pi*i t/256}

__global__ void k_twinit() {
    int t = threadIdx.x;
    float s, c;
    sincospif(-(float)t * (1.0f / 128.0f), &s, &c);
    g_tw[t] = make_float2(c, s);
}

// padded shared index: +1 float2 per 16 (breaks 8-way store conflicts)
#define SP(i) ((i) + ((i) >> 4))

template <bool INV>
__device__ __forceinline__ float2 twmul(float2 a, float2 w) {
    float wy = INV ? -w.y : w.y;
    return make_float2(a.x * w.x - a.y * wy, a.x * wy + a.y * w.x);
}

template <bool INV>
__device__ __forceinline__ void bfly4(float2 v[4]) {
    float2 t0 = make_float2(v[0].x + v[2].x, v[0].y + v[2].y);
    float2 t1 = make_float2(v[0].x - v[2].x, v[0].y - v[2].y);
    float2 t2 = make_float2(v[1].x + v[3].x, v[1].y + v[3].y);
    float2 t3 = make_float2(v[1].x - v[3].x, v[1].y - v[3].y);
    v[0] = make_float2(t0.x + t2.x, t0.y + t2.y);
    v[2] = make_float2(t0.x - t2.x, t0.y - t2.y);
    if (!INV) {
        v[1] = make_float2(t1.x + t3.y, t1.y - t3.x);
        v[3] = make_float2(t1.x - t3.y, t1.y + t3.x);
    } else {
        v[1] = make_float2(t1.x - t3.y, t1.y + t3.x);
        v[3] = make_float2(t1.x + t3.y, t1.y - t3.x);
    }
}

// ---------------------------------------------------------------------------
// N=256 radix-4 Stockham. t in [0,64). Input v[r] = in[t+64r];
// output v[r] = out[t+64r]. s0/s1: padded buffers of >=272 float2.
// ---------------------------------------------------------------------------
template <bool INV>
__device__ __forceinline__ void fft256_core(float2 v[4], float2* s0, float2* s1,
                                            int t, const float2* tw) {
    bfly4<INV>(v);                                   // stage 1, Ns=1
    s0[SP(4 * t + 0)] = v[0]; s0[SP(4 * t + 1)] = v[1];
    s0[SP(4 * t + 2)] = v[2]; s0[SP(4 * t + 3)] = v[3];
    __syncthreads();
    {                                                // stage 2, Ns=4
        int jm = t & 3;
        v[0] = s0[SP(t)];       v[1] = s0[SP(t + 64)];
        v[2] = s0[SP(t + 128)]; v[3] = s0[SP(t + 192)];
        v[1] = twmul<INV>(v[1], tw[16 * jm]);
        v[2] = twmul<INV>(v[2], tw[32 * jm]);
        v[3] = twmul<INV>(v[3], tw[48 * jm]);
        bfly4<INV>(v);
        int d = 4 * (t - jm) + jm;
        s1[SP(d)] = v[0]; s1[SP(d + 4)] = v[1];
        s1[SP(d + 8)] = v[2]; s1[SP(d + 12)] = v[3];
    }
    __syncthreads();
    {                                                // stage 3, Ns=16
        int jm = t & 15;
        v[0] = s1[SP(t)];       v[1] = s1[SP(t + 64)];
        v[2] = s1[SP(t + 128)]; v[3] = s1[SP(t + 192)];
        v[1] = twmul<INV>(v[1], tw[4 * jm]);
        v[2] = twmul<INV>(v[2], tw[8 * jm]);
        v[3] = twmul<INV>(v[3], tw[12 * jm]);
        bfly4<INV>(v);
        int d = 4 * (t - jm) + jm;
        s0[SP(d)] = v[0]; s0[SP(d + 16)] = v[1];
        s0[SP(d + 32)] = v[2]; s0[SP(d + 48)] = v[3];
    }
    __syncthreads();
    {                                                // stage 4, Ns=64
        v[0] = s0[SP(t)];       v[1] = s0[SP(t + 64)];
        v[2] = s0[SP(t + 128)]; v[3] = s0[SP(t + 192)];
        v[1] = twmul<INV>(v[1], tw[t]);
        v[2] = twmul<INV>(v[2], tw[2 * t]);
        v[3] = twmul<INV>(v[3], tw[3 * t]);
        bfly4<INV>(v);                               // out at t+64r
    }
}

// ---------------------------------------------------------------------------
// N=128: 3 radix-4 stages + 1 radix-2. t in [0,32). Input v[r]=in[t+32r];
// output v[0..3] = out[t], out[t+32], out[t+64], out[t+96].
// ---------------------------------------------------------------------------
template <bool INV>
__device__ __forceinline__ void fft128_core(float2 v[4], float2* s0, float2* s1,
                                            int t, const float2* tw) {
    bfly4<INV>(v);                                   // Ns=1
    s0[SP(4 * t + 0)] = v[0]; s0[SP(4 * t + 1)] = v[1];
    s0[SP(4 * t + 2)] = v[2]; s0[SP(4 * t + 3)] = v[3];
    __syncthreads();
    {                                                // Ns=4
        int jm = t & 3;
        v[0] = s0[SP(t)];      v[1] = s0[SP(t + 32)];
        v[2] = s0[SP(t + 64)]; v[3] = s0[SP(t + 96)];
        v[1] = twmul<INV>(v[1], tw[16 * jm]);
        v[2] = twmul<INV>(v[2], tw[32 * jm]);
        v[3] = twmul<INV>(v[3], tw[48 * jm]);
        bfly4<INV>(v);
        int d = 4 * (t - jm) + jm;
        s1[SP(d)] = v[0]; s1[SP(d + 4)] = v[1];
        s1[SP(d + 8)] = v[2]; s1[SP(d + 12)] = v[3];
    }
    __syncthreads();
    {                                                // Ns=16
        int jm = t & 15;
        v[0] = s1[SP(t)];      v[1] = s1[SP(t + 32)];
        v[2] = s1[SP(t + 64)]; v[3] = s1[SP(t + 96)];
        v[1] = twmul<INV>(v[1], tw[4 * jm]);
        v[2] = twmul<INV>(v[2], tw[8 * jm]);
        v[3] = twmul<INV>(v[3], tw[12 * jm]);
        bfly4<INV>(v);
        int d = 4 * (t - jm) + jm;
        s0[SP(d)] = v[0]; s0[SP(d + 16)] = v[1];
        s0[SP(d + 32)] = v[2]; s0[SP(d + 48)] = v[3];
    }
    __syncthreads();
    {                                                // radix-2, Ns=64
        float2 a0 = s0[SP(t)],      b0 = s0[SP(t + 64)];
        float2 a1 = s0[SP(t + 32)], b1 = s0[SP(t + 96)];
        float2 bw0 = twmul<INV>(b0, tw[2 * t]);
        float2 bw1 = twmul<INV>(b1, tw[2 * (t + 32)]);
        v[0] = make_float2(a0.x + bw0.x, a0.y + bw0.y);
        v[2] = make_float2(a0.x - bw0.x, a0.y - bw0.y);
        v[1] = make_float2(a1.x + bw1.x, a1.y + bw1.y);
        v[3] = make_float2(a1.x - bw1.x, a1.y - bw1.y);
    }
}

// ---------------------------------------------------------------------------
// FB step A: row FFTs of the 25 nonzero otf rows per plane.
// otf row i = (r-12) mod 256 holds psf[r][c] at j=(c-12) mod 256.
// Writes g_SC as Rf[p][r][u]  (p*6400 + r*256 + u).
// ---------------------------------------------------------------------------
__global__ void k_fbrows(const float* __restrict__ psf, float2* __restrict__ Rf) {
    __shared__ float2 sbuf[8][2 * 272];
    __shared__ float2 stw[256];
    int t = threadIdx.x, ry = threadIdx.y;
    int lt = ry * 64 + t;
    if (lt < 256) stw[lt] = g_tw[lt];
    int gr = blockIdx.x * 8 + ry;          // 0..6399
    int p = gr / 25, r = gr - p * 25;
    const float* kp = psf + p * 625 + r * 25;
    float2 v[4];
#pragma unroll
    for (int q = 0; q < 4; ++q) {
        int j = t + 64 * q;
        int c = (j + 12) & 255;
        v[q] = make_float2(c < 25 ? kp[c] : 0.f, 0.f);
    }
    __syncthreads();   // stw ready (stage1 uses no tw, but cheap & safe)
    fft256_core<false>(v, sbuf[ry], sbuf[ry] + 272, t, stw);
    float2* d = Rf + gr * 256;
    d[t] = v[0]; d[t + 64] = v[1]; d[t + 128] = v[2]; d[t + 192] = v[3];
}

// ---------------------------------------------------------------------------
// FB step B: column transform = 25-term direct DFT, writing FB^T.
// FB^T[p][u][v] = sum_r Rf[p][r][u] * e^{-2pi i v (r-12)/256}.
// Hermitian: FB^T[256-u][256-v] = conj(FB^T[u][v]) (psf real) — direct compute
// for u in [0,160), mirror-write covers the rest. thread = v (0..255).
// ---------------------------------------------------------------------------
__global__ void k_fbcol(const float2* __restrict__ Rf, float2* __restrict__ FBt) {
    __shared__ float2 sRf[25][32];
    __shared__ float2 stw[256];
    int p = blockIdx.y;
    int u0 = blockIdx.x * 32;              // blockIdx.x in 0..4
    int v = threadIdx.x;                   // 256 threads = 256 v values
    stw[v] = g_tw[v];
    for (int e = v; e < 800; e += 256) {
        int r = e >> 5, uu = e & 31;
        sRf[r][uu] = Rf[p * 6400 + r * 256 + u0 + uu];
    }
    __syncthreads();

    float2 twr[25];
#pragma unroll
    for (int r = 0; r < 25; ++r)
        twr[r] = stw[(v * (r - 12)) & 255];

    bool mir = (blockIdx.x < 4);
    int vm = (256 - v) & 255;
#pragma unroll 2
    for (int u = 0; u < 32; ++u) {
        float2 acc = make_float2(0.f, 0.f);
#pragma unroll
        for (int r = 0; r < 25; ++r) {
            float2 a = sRf[r][u];
            acc.x += a.x * twr[r].x - a.y * twr[r].y;
            acc.y += a.x * twr[r].y + a.y * twr[r].x;
        }
        int ug = u0 + u;
        FBt[(p << 16) + (ug << 8) + v] = acc;
        if (mir && ug != 0)
            FBt[(p << 16) + ((256 - ug) << 8) + vm] = make_float2(acc.x, -acc.y);
    }
}

// ---------------------------------------------------------------------------
// x row FFTs (N=128, real input) -> SB region 0
// ---------------------------------------------------------------------------
__global__ void k_x128(const float* __restrict__ x, float2* __restrict__ dst) {
    __shared__ float2 sbuf[8][2 * 136];
    __shared__ float2 stw[256];
    int t = threadIdx.x, ry = threadIdx.y;     // (32,8)
    int lt = ry * 32 + t;
    stw[lt] = g_tw[lt];
    int gr = blockIdx.x * 8 + ry;
    const float* xs = x + gr * 128;
    float2 v[4];
#pragma unroll
    for (int q = 0; q < 4; ++q) v[q] = make_float2(xs[t + 32 * q], 0.f);
    __syncthreads();
    fft128_core<false>(v, sbuf[ry], sbuf[ry] + 136, t, stw);
    float2* d = dst + gr * 128;
    d[t] = v[0]; d[t + 32] = v[1]; d[t + 64] = v[2]; d[t + 96] = v[3];
}

// complex 128-FFT rows (second pass of x) -> Fx^T in SC
__global__ void k_cfft128(const float2* __restrict__ src, float2* __restrict__ dst) {
    __shared__ float2 sbuf[8][2 * 136];
    __shared__ float2 stw[256];
    int t = threadIdx.x, ry = threadIdx.y;
    int lt = ry * 32 + t;
    stw[lt] = g_tw[lt];
    int gr = blockIdx.x * 8 + ry;
    const float2* s = src + gr * 128;
    float2 v[4];
#pragma unroll
    for (int q = 0; q < 4; ++q) v[q] = s[t + 32 * q];
    __syncthreads();
    fft128_core<false>(v, sbuf[ry], sbuf[ry] + 136, t, stw);
    float2* d = dst + gr * 128;
    d[t] = v[0]; d[t + 32] = v[1]; d[t + 64] = v[2]; d[t + 96] = v[3];
}

// complex 256-FFT rows, templated direction, scaled output
template <bool INV>
__global__ void k_cfft256(const float2* __restrict__ src, float2* __restrict__ dst,
                          float scale) {
    __shared__ float2 sbuf[8][2 * 272];
    __shared__ float2 stw[256];
    int t = threadIdx.x, ry = threadIdx.y;     // (64,8)
    int lt = ry * 64 + t;
    if (lt < 256) stw[lt] = g_tw[lt];
    int gr = blockIdx.x * 8 + ry;
    const float2* s = src + gr * 256;
    float2 v[4];
#pragma unroll
    for (int q = 0; q < 4; ++q) v[q] = s[t + 64 * q];
    __syncthreads();
    fft256_core<INV>(v, sbuf[ry], sbuf[ry] + 272, t, stw);
    float2* d = dst + gr * 256;
#pragma unroll
    for (int q = 0; q < 4; ++q)
        d[t + 64 * q] = make_float2(v[q].x * scale, v[q].y * scale);
}

// final inverse row pass: real part only -> out
__global__ void k_ifinal(const float2* __restrict__ src, float* __restrict__ out) {
    __shared__ float2 sbuf[8][2 * 272];
    __shared__ float2 stw[256];
    int t = threadIdx.x, ry = threadIdx.y;
    int lt = ry * 64 + t;
    if (lt < 256) stw[lt] = g_tw[lt];
    int gr = blockIdx.x * 8 + ry;
    const float2* s = src + gr * 256;
    float2 v[4];
#pragma unroll
    for (int q = 0; q < 4; ++q) v[q] = s[t + 64 * q];
    __syncthreads();
    fft256_core<true>(v, sbuf[ry], sbuf[ry] + 272, t, stw);
    const float sc = 1.0f / 256.0f;
    float* d = out + gr * 256;
    d[t] = v[0].x * sc; d[t + 64] = v[1].x * sc;
    d[t + 128] = v[2].x * sc; d[t + 192] = v[3].x * sc;
}

// ---------------------------------------------------------------------------
// Per-plane tile transpose
// ---------------------------------------------------------------------------
template <int N>
__global__ void k_transpose(const float2* __restrict__ src, float2* __restrict__ dst) {
    __shared__ float2 tile[32][33];
    int p = blockIdx.z;
    const float2* s = src + p * N * N;
    float2* d = dst + p * N * N;
    int x0 = blockIdx.x * 32, y0 = blockIdx.y * 32;
    int tx = threadIdx.x;
    for (int ty = threadIdx.y; ty < 32; ty += blockDim.y)
        tile[ty][tx] = s[(y0 + ty) * N + x0 + tx];
    __syncthreads();
    for (int ty = threadIdx.y; ty < 32; ty += blockDim.y)
        d[(x0 + ty) * N + y0 + tx] = tile[tx][ty];
}

// ---------------------------------------------------------------------------
// Fused frequency-domain solve (all arrays stored transposed).
// ---------------------------------------------------------------------------
__device__ __forceinline__ float2 cmulf(float2 a, float2 b) {
    return make_float2(a.x * b.x - a.y * b.y, a.x * b.y + a.y * b.x);
}

__global__ void k_mid(const float* __restrict__ alpha) {
    int idx = blockIdx.x * blockDim.x + threadIdx.x;
    int u = idx & 127;
    int v = (idx >> 7) & 127;
    int p = idx >> 14;

    float a = alpha[p & (NCH - 1)];
    float be = 1.f / (1.f + expf(9.f - a)) + 1e-3f;

    float2 fx = g_SC[(p << 14) + (v << 7) + u];
    int base = p << 16;

    float2 twu0 = g_tw[u], twu1 = g_tw[u + 128];
    float2 twv0 = g_tw[v], twv1 = g_tw[v + 128];

    float2 FB[4], FR[4];
    float2 sBR = make_float2(0.f, 0.f);
    float sW = 0.f;
#pragma unroll
    for (int q = 0; q < 4; ++q) {
        int qa = q >> 1, qb = q & 1;
        int V = v + (qa << 7), U = u + (qb << 7);
        float2 fb = g_SA[base + (V << 8) + U];
        FB[q] = fb;
        float2 tu = qb ? twu1 : twu0;
        float2 tv = qa ? twv1 : twv0;
        float2 pu = make_float2(1.f + tu.x, tu.y);
        float2 pv = make_float2(1.f + tv.x, tv.y);
        float2 P = cmulf(pu, pv);
        float2 m = make_float2(fb.x + be * P.x, -fb.y + be * P.y);
        float2 fr = cmulf(fx, m);
        FR[q] = fr;
        sBR.x += fb.x * fr.x - fb.y * fr.y;
        sBR.y += fb.x * fr.y + fb.y * fr.x;
        sW += fb.x * fb.x + fb.y * fb.y;
    }
    sBR.x *= 0.25f; sBR.y *= 0.25f; sW *= 0.25f;
    float inv = 1.f / (sW + be);
    float2 iw = make_float2(sBR.x * inv, sBR.y * inv);
    float ibe = 1.f / be;
#pragma unroll
    for (int q = 0; q < 4; ++q) {
        int qa = q >> 1, qb = q & 1;
        int V = v + (qa << 7), U = u + (qb << 7);
        float2 tmp = make_float2(FB[q].x * iw.x + FB[q].y * iw.y,
                                 FB[q].x * iw.y - FB[q].y * iw.x);
        g_SB[base + (V << 8) + U] =
            make_float2((FR[q].x - tmp.x) * ibe, (FR[q].y - tmp.y) * ibe);
    }
}

// ---------------------------------------------------------------------------
extern "C" void kernel_launch(void* const* d_in, const int* in_sizes, int n_in,
                              void* d_out, int out_size) {
    const float* x     = (const float*)d_in[0];
    const float* psf   = (const float*)d_in[1];
    const float* alpha = (const float*)d_in[2];
    float* out = (float*)d_out;

    float2 *SA, *SB, *SC;
    cudaGetSymbolAddress((void**)&SA, g_SA);
    cudaGetSymbolAddress((void**)&SB, g_SB);
    cudaGetSymbolAddress((void**)&SC, g_SC);

    k_twinit<<<1, 256>>>();

    // FB^T -> SA (via 25-row FFTs in SC, then direct 25-term column DFT)
    k_fbrows<<<800, dim3(64, 8)>>>(psf, SC);
    k_fbcol<<<dim3(5, NPLANES), 256>>>(SC, SA);

    // Fx^T -> SC
    k_x128<<<NPLANES * 128 / 8, dim3(32, 8)>>>(x, SB);
    k_transpose<128><<<dim3(4, 4, NPLANES), dim3(32, 8)>>>(SB, SB + NPLANES * 128 * 128);
    k_cfft128<<<NPLANES * 128 / 8, dim3(32, 8)>>>(SB + NPLANES * 128 * 128, SC);

    // frequency-domain solve -> SB = FX^T
    k_mid<<<NPLANES * 128 * 128 / 256, 256>>>(alpha);

    // out = real(ifft2(FX))
    k_cfft256<true><<<NPLANES * 256 / 8, dim3(64, 8)>>>(SB, SA, 1.0f / 256.0f);
    k_transpose<256><<<dim3(8, 8, NPLANES), dim3(32, 8)>>>(SA, SB);
    k_ifinal<<<NPLANES * 256 / 8, dim3(64, 8)>>>(SB, out);
}

// round 4
// speedup vs baseline: 2.6743x; 1.5205x over previous
#include <cuda_runtime.h>
#include <math.h>

// Shapes fixed: x (4,64,128,128), k (4,64,25,25), alpha (1,64,1,1), sf=2.
// Output (4,64,256,256) fp32.
#define NPLANES 256
#define NCH 64
#define HSTRIDE (129 * 256)   // half-spectrum plane stride (rows 0..128)

// ---------------------------------------------------------------------------
// Scratch (__device__ globals; allocation-free)
// ---------------------------------------------------------------------------
__device__ float2 g_SA[NPLANES * HSTRIDE];     // 67.6 MB : FB half, then G half
__device__ float2 g_SB[NPLANES * HSTRIDE];     // 67.6 MB : x row-FFTs, then FX half
__device__ float2 g_SC[NPLANES * 128 * 128];   // 33.5 MB : Rf, then Fx^T
__device__ float2 g_tw[256];                   // e^{-2*pi*i t/256}

__global__ void k_twinit() {
    int t = threadIdx.x;
    float s, c;
    sincospif(-(float)t * (1.0f / 128.0f), &s, &c);
    g_tw[t] = make_float2(c, s);
}

// padded shared index: +1 float2 per 16 (breaks 8-way store conflicts)
#define SP(i) ((i) + ((i) >> 4))

template <bool INV>
__device__ __forceinline__ float2 twmul(float2 a, float2 w) {
    float wy = INV ? -w.y : w.y;
    return make_float2(a.x * w.x - a.y * wy, a.x * wy + a.y * w.x);
}

template <bool INV>
__device__ __forceinline__ void bfly4(float2 v[4]) {
    float2 t0 = make_float2(v[0].x + v[2].x, v[0].y + v[2].y);
    float2 t1 = make_float2(v[0].x - v[2].x, v[0].y - v[2].y);
    float2 t2 = make_float2(v[1].x + v[3].x, v[1].y + v[3].y);
    float2 t3 = make_float2(v[1].x - v[3].x, v[1].y - v[3].y);
    v[0] = make_float2(t0.x + t2.x, t0.y + t2.y);
    v[2] = make_float2(t0.x - t2.x, t0.y - t2.y);
    if (!INV) {
        v[1] = make_float2(t1.x + t3.y, t1.y - t3.x);
        v[3] = make_float2(t1.x - t3.y, t1.y + t3.x);
    } else {
        v[1] = make_float2(t1.x - t3.y, t1.y + t3.x);
        v[3] = make_float2(t1.x + t3.y, t1.y - t3.x);
    }
}

// ---------------------------------------------------------------------------
// N=256 radix-4 Stockham; lane = 64 threads (2 warps) -> __syncthreads.
// ---------------------------------------------------------------------------
template <bool INV>
__device__ __forceinline__ void fft256_core(float2 v[4], float2* s0, float2* s1,
                                            int t, const float2* tw) {
    bfly4<INV>(v);
    s0[SP(4 * t + 0)] = v[0]; s0[SP(4 * t + 1)] = v[1];
    s0[SP(4 * t + 2)] = v[2]; s0[SP(4 * t + 3)] = v[3];
    __syncthreads();
    {
        int jm = t & 3;
        v[0] = s0[SP(t)];       v[1] = s0[SP(t + 64)];
        v[2] = s0[SP(t + 128)]; v[3] = s0[SP(t + 192)];
        v[1] = twmul<INV>(v[1], tw[16 * jm]);
        v[2] = twmul<INV>(v[2], tw[32 * jm]);
        v[3] = twmul<INV>(v[3], tw[48 * jm]);
        bfly4<INV>(v);
        int d = 4 * (t - jm) + jm;
        s1[SP(d)] = v[0]; s1[SP(d + 4)] = v[1];
        s1[SP(d + 8)] = v[2]; s1[SP(d + 12)] = v[3];
    }
    __syncthreads();
    {
        int jm = t & 15;
        v[0] = s1[SP(t)];       v[1] = s1[SP(t + 64)];
        v[2] = s1[SP(t + 128)]; v[3] = s1[SP(t + 192)];
        v[1] = twmul<INV>(v[1], tw[4 * jm]);
        v[2] = twmul<INV>(v[2], tw[8 * jm]);
        v[3] = twmul<INV>(v[3], tw[12 * jm]);
        bfly4<INV>(v);
        int d = 4 * (t - jm) + jm;
        s0[SP(d)] = v[0]; s0[SP(d + 16)] = v[1];
        s0[SP(d + 32)] = v[2]; s0[SP(d + 48)] = v[3];
    }
    __syncthreads();
    {
        v[0] = s0[SP(t)];       v[1] = s0[SP(t + 64)];
        v[2] = s0[SP(t + 128)]; v[3] = s0[SP(t + 192)];
        v[1] = twmul<INV>(v[1], tw[t]);
        v[2] = twmul<INV>(v[2], tw[2 * t]);
        v[3] = twmul<INV>(v[3], tw[3 * t]);
        bfly4<INV>(v);
    }
}

// ---------------------------------------------------------------------------
// N=128 radix-4x3 + radix-2; lane = exactly one warp -> __syncwarp only.
// ---------------------------------------------------------------------------
template <bool INV>
__device__ __forceinline__ void fft128_core(float2 v[4], float2* s0, float2* s1,
                                            int t, const float2* tw) {
    bfly4<INV>(v);
    s0[SP(4 * t + 0)] = v[0]; s0[SP(4 * t + 1)] = v[1];
    s0[SP(4 * t + 2)] = v[2]; s0[SP(4 * t + 3)] = v[3];
    __syncwarp();
    {
        int jm = t & 3;
        v[0] = s0[SP(t)];      v[1] = s0[SP(t + 32)];
        v[2] = s0[SP(t + 64)]; v[3] = s0[SP(t + 96)];
        v[1] = twmul<INV>(v[1], tw[16 * jm]);
        v[2] = twmul<INV>(v[2], tw[32 * jm]);
        v[3] = twmul<INV>(v[3], tw[48 * jm]);
        bfly4<INV>(v);
        int d = 4 * (t - jm) + jm;
        s1[SP(d)] = v[0]; s1[SP(d + 4)] = v[1];
        s1[SP(d + 8)] = v[2]; s1[SP(d + 12)] = v[3];
    }
    __syncwarp();
    {
        int jm = t & 15;
        v[0] = s1[SP(t)];      v[1] = s1[SP(t + 32)];
        v[2] = s1[SP(t + 64)]; v[3] = s1[SP(t + 96)];
        v[1] = twmul<INV>(v[1], tw[4 * jm]);
        v[2] = twmul<INV>(v[2], tw[8 * jm]);
        v[3] = twmul<INV>(v[3], tw[12 * jm]);
        bfly4<INV>(v);
        int d = 4 * (t - jm) + jm;
        s0[SP(d)] = v[0]; s0[SP(d + 16)] = v[1];
        s0[SP(d + 32)] = v[2]; s0[SP(d + 48)] = v[3];
    }
    __syncwarp();
    {
        float2 a0 = s0[SP(t)],      b0 = s0[SP(t + 64)];
        float2 a1 = s0[SP(t + 32)], b1 = s0[SP(t + 96)];
        float2 bw0 = twmul<INV>(b0, tw[2 * t]);
        float2 bw1 = twmul<INV>(b1, tw[2 * (t + 32)]);
        v[0] = make_float2(a0.x + bw0.x, a0.y + bw0.y);
        v[2] = make_float2(a0.x - bw0.x, a0.y - bw0.y);
        v[1] = make_float2(a1.x + bw1.x, a1.y + bw1.y);
        v[3] = make_float2(a1.x - bw1.x, a1.y - bw1.y);
    }
}

// ---------------------------------------------------------------------------
// FB step A: row FFTs (N=256) of the 25 nonzero otf rows per plane -> Rf (SC).
// ---------------------------------------------------------------------------
__global__ void k_fbrows(const float* __restrict__ psf, float2* __restrict__ Rf) {
    __shared__ float2 sbuf[8][2 * 272];
    __shared__ float2 stw[256];
    int t = threadIdx.x, ry = threadIdx.y;   // (64,8)
    int lt = ry * 64 + t;
    if (lt < 256) stw[lt] = g_tw[lt];
    int gr = blockIdx.x * 8 + ry;            // 0..6399
    int p = gr / 25, r = gr - p * 25;
    const float* kp = psf + p * 625 + r * 25;
    float2 v[4];
#pragma unroll
    for (int q = 0; q < 4; ++q) {
        int c = (t + 64 * q + 12) & 255;
        v[q] = make_float2(c < 25 ? kp[c] : 0.f, 0.f);
    }
    __syncthreads();
    fft256_core<false>(v, sbuf[ry], sbuf[ry] + 272, t, stw);
    float2* d = Rf + gr * 256;
    d[t] = v[0]; d[t + 64] = v[1]; d[t + 128] = v[2]; d[t + 192] = v[3];
}

// ---------------------------------------------------------------------------
// FB step B: 25-term direct column DFT -> FB^T rows 0..128 ONLY (Hermitian).
// FB^T[p][u][v] = sum_r Rf[p][r][u] * tw[(v*(r-12)) mod 256]
// (first index = width-frequency, second = height-frequency)
// ---------------------------------------------------------------------------
__global__ void k_fbcol(const float2* __restrict__ Rf, float2* __restrict__ FBt) {
    __shared__ float2 sRf[25][32];
    __shared__ float2 stw[256];
    int p = blockIdx.y;
    int u0 = blockIdx.x * 32;        // 0..4 -> u in [0,160); keep <=128
    int v = threadIdx.x;             // 256 threads
    stw[v] = g_tw[v];
    for (int e = v; e < 800; e += 256) {
        int r = e >> 5, uu = e & 31;
        sRf[r][uu] = Rf[p * 6400 + r * 256 + u0 + uu];
    }
    __syncthreads();

    float2 twr[25];
#pragma unroll
    for (int r = 0; r < 25; ++r)
        twr[r] = stw[(v * (r - 12)) & 255];

#pragma unroll 2
    for (int u = 0; u < 32; ++u) {
        int ug = u0 + u;
        if (ug > 128) break;
        float2 acc = make_float2(0.f, 0.f);
#pragma unroll
        for (int r = 0; r < 25; ++r) {
            float2 a = sRf[r][u];
            acc.x += a.x * twr[r].x - a.y * twr[r].y;
            acc.y += a.x * twr[r].y + a.y * twr[r].x;
        }
        FBt[p * HSTRIDE + ug * 256 + v] = acc;
    }
}

// ---------------------------------------------------------------------------
// x row FFTs: pack TWO real rows per complex 128-FFT. Writes R1[p][y][u] (SB).
// ---------------------------------------------------------------------------
__global__ void k_x128p(const float* __restrict__ x, float2* __restrict__ R1) {
    __shared__ float2 sbuf[8][2 * 136];
    __shared__ float2 stw[256];
    int t = threadIdx.x, ry = threadIdx.y;     // (32,8)
    int lt = ry * 32 + t;
    stw[lt] = g_tw[lt];
    int pr = blockIdx.x * 8 + ry;              // pair id, [0, 256*64)
    const float* xa = x + pr * 256;            // rows 2j, 2j+1 of plane
    float2 v[4];
#pragma unroll
    for (int q = 0; q < 4; ++q)
        v[q] = make_float2(xa[t + 32 * q], xa[128 + t + 32 * q]);
    __syncthreads();   // stw visible to all
    fft128_core<false>(v, sbuf[ry], sbuf[ry] + 136, t, stw);
    float2* s0 = sbuf[ry];
#pragma unroll
    for (int q = 0; q < 4; ++q) s0[SP(t + 32 * q)] = v[q];
    __syncwarp();
    float2* da = R1 + pr * 256;
    float2* db = da + 128;
#pragma unroll
    for (int q = 0; q < 4; ++q) {
        int k = t + 32 * q;
        float2 Zk = s0[SP(k)];
        float2 Zm = s0[SP((128 - k) & 127)];
        da[k] = make_float2(0.5f * (Zk.x + Zm.x), 0.5f * (Zk.y - Zm.y));
        db[k] = make_float2(0.5f * (Zk.y + Zm.y), 0.5f * (Zm.x - Zk.x));
    }
}

// ---------------------------------------------------------------------------
// Fused transpose + column FFT of x. Reads R1[p][y][u] (SB), FFT over y,
// writes Fx^T[p][u][vh] (SC)  — TRANSPOSED output to match FB^T layout.
// ---------------------------------------------------------------------------
__global__ void k_xcol(const float2* __restrict__ R1, float2* __restrict__ Fx) {
    __shared__ float2 tile[128][17];
    __shared__ float2 sbuf[8][2 * 136];
    __shared__ float2 stw[256];
    int t = threadIdx.x, f = threadIdx.y;      // (32,8)
    int tid = f * 32 + t;
    stw[tid] = g_tw[tid];
    int p = blockIdx.y, u0 = blockIdx.x * 16;
    const float2* Rp = R1 + p * 16384;
#pragma unroll
    for (int it = 0; it < 8; ++it) {
        int idx = it * 256 + tid;
        int y = idx >> 4, ff = idx & 15;
        tile[y][ff] = Rp[y * 128 + u0 + ff];
    }
    __syncthreads();
#pragma unroll
    for (int rep = 0; rep < 2; ++rep) {
        int fc = f + 8 * rep;
        float2 v[4];
#pragma unroll
        for (int q = 0; q < 4; ++q) v[q] = tile[t + 32 * q][fc];
        fft128_core<false>(v, sbuf[f], sbuf[f] + 136, t, stw);
        __syncwarp();
#pragma unroll
        for (int q = 0; q < 4; ++q) tile[t + 32 * q][fc] = v[q];
    }
    __syncthreads();
    // transposed write: Fx^T[u0+ff][r], r fast -> coalesced
    float2* Fp = Fx + p * 16384;
#pragma unroll
    for (int it = 0; it < 8; ++it) {
        int idx = it * 256 + tid;
        int r = idx & 127, ff = idx >> 7;     // ff in [0,16) over 8 iters
        Fp[(u0 + ff) * 128 + r] = tile[r][ff];
    }
}

// ---------------------------------------------------------------------------
// Fused frequency-domain solve. All spectra width-freq major ("^T").
// FB stored half (rows 0..128), mirror-read via Hermitian symmetry.
// FX written half (rows 0..128 of SB).
// ---------------------------------------------------------------------------
__device__ __forceinline__ float2 cmulf(float2 a, float2 b) {
    return make_float2(a.x * b.x - a.y * b.y, a.x * b.y + a.y * b.x);
}

__global__ void k_mid(const float* __restrict__ alpha) {
    int idx = blockIdx.x * blockDim.x + threadIdx.x;
    int u = idx & 127;             // height-freq (contiguous)
    int v = (idx >> 7) & 127;      // width-freq (major)
    int p = idx >> 14;

    float a = alpha[p & (NCH - 1)];
    float be = 1.f / (1.f + expf(9.f - a)) + 1e-3f;

    float2 fx = g_SC[(p << 14) + (v << 7) + u];
    const float2* FBp = g_SA + p * HSTRIDE;

    float2 FB[4];
    FB[0] = FBp[v * 256 + u];            // (a=0,b=0) V=v,   U=u
    FB[1] = FBp[v * 256 + u + 128];      // (a=0,b=1) V=v,   U=u+128
    if (v == 0) {
        FB[2] = FBp[128 * 256 + u];
        FB[3] = FBp[128 * 256 + u + 128];
    } else {
        const float2* rm = FBp + (128 - v) * 256;
        float2 t0 = rm[(256 - u) & 255];  // conj -> (a=1,b=0)
        float2 t1 = rm[128 - u];          // conj -> (a=1,b=1)
        FB[2] = make_float2(t0.x, -t0.y);
        FB[3] = make_float2(t1.x, -t1.y);
    }

    float2 twu0 = g_tw[u], twu1 = g_tw[u + 128];
    float2 twv0 = g_tw[v], twv1 = g_tw[v + 128];

    float2 FR[4];
    float2 sBR = make_float2(0.f, 0.f);
    float sW = 0.f;
#pragma unroll
    for (int q = 0; q < 4; ++q) {
        int qa = q >> 1, qb = q & 1;
        float2 fb = FB[q];
        float2 tu = qb ? twu1 : twu0;
        float2 tv = qa ? twv1 : twv0;
        float2 pu = make_float2(1.f + tu.x, tu.y);
        float2 pv = make_float2(1.f + tv.x, tv.y);
        float2 P = cmulf(pu, pv);
        float2 m = make_float2(fb.x + be * P.x, -fb.y + be * P.y);
        float2 fr = cmulf(fx, m);
        FR[q] = fr;
        sBR.x += fb.x * fr.x - fb.y * fr.y;
        sBR.y += fb.x * fr.y + fb.y * fr.x;
        sW += fb.x * fb.x + fb.y * fb.y;
    }
    sBR.x *= 0.25f; sBR.y *= 0.25f; sW *= 0.25f;
    float inv = 1.f / (sW + be);
    float2 iw = make_float2(sBR.x * inv, sBR.y * inv);
    float ibe = 1.f / be;

    float2 Q[4];
#pragma unroll
    for (int q = 0; q < 4; ++q) {
        float2 tmp = make_float2(FB[q].x * iw.x + FB[q].y * iw.y,
                                 FB[q].x * iw.y - FB[q].y * iw.x);
        Q[q] = make_float2((FR[q].x - tmp.x) * ibe, (FR[q].y - tmp.y) * ibe);
    }
    float2* W = g_SB + p * HSTRIDE;
    W[v * 256 + u]       = Q[0];
    W[v * 256 + u + 128] = Q[1];
    if (v == 0) {
        W[128 * 256 + u]       = Q[2];
        W[128 * 256 + u + 128] = Q[3];
    }
}

// ---------------------------------------------------------------------------
// Inverse 256-FFT along the contiguous (height-freq) index, rows A in [0,129).
// SB (FX half) -> SA (G half):  G[A][y], A = width-freq, y = spatial height.
// ---------------------------------------------------------------------------
__global__ void k_half256(const float2* __restrict__ src, float2* __restrict__ dst) {
    __shared__ float2 sbuf[8][2 * 272];
    __shared__ float2 stw[256];
    int t = threadIdx.x, ry = threadIdx.y;    // (64,8)
    int lt = ry * 64 + t;
    if (lt < 256) stw[lt] = g_tw[lt];
    int gr = blockIdx.x * 8 + ry;             // [0, 256*129)
    int p = gr / 129, A = gr - p * 129;
    const float2* s = src + p * HSTRIDE + A * 256;
    float2 v[4];
#pragma unroll
    for (int q = 0; q < 4; ++q) v[q] = s[t + 64 * q];
    __syncthreads();
    fft256_core<true>(v, sbuf[ry], sbuf[ry] + 272, t, stw);
    float2* d = dst + p * HSTRIDE + A * 256;
    d[t] = v[0]; d[t + 64] = v[1]; d[t + 128] = v[2]; d[t + 192] = v[3];
}

// ---------------------------------------------------------------------------
// Final: fused transpose + Hermitian-packed real inverse along width
// (length 256 via one complex 128-FFT per output row). Tile 129x16.
// out[p][y][x] written as float2 pairs (cols 2n,2n+1).
// ---------------------------------------------------------------------------
__global__ void k_final(const float2* __restrict__ G, float2* __restrict__ out2) {
    __shared__ float2 tile[129][17];
    __shared__ float2 sbuf[8][2 * 136];
    __shared__ float2 stw[256];
    int t = threadIdx.x, f = threadIdx.y;     // (32,8)
    int tid = f * 32 + t;
    stw[tid] = g_tw[tid];
    int p = blockIdx.y, x0 = blockIdx.x * 16;
    const float2* Gp = G + p * HSTRIDE;
#pragma unroll
    for (int it = 0; it < 9; ++it) {
        int idx = it * 256 + tid;
        int A = idx >> 4, ff = idx & 15;
        if (A < 129) tile[A][ff] = Gp[A * 256 + x0 + ff];
    }
    __syncthreads();
    const float s = 1.0f / 65536.0f;
#pragma unroll
    for (int rep = 0; rep < 2; ++rep) {
        int fc = f + 8 * rep;
        float2 v[4];
#pragma unroll
        for (int q = 0; q < 4; ++q) {
            int k = t + 32 * q;
            float2 hk = tile[k][fc];
            float2 hm = tile[128 - k][fc];
            float2 c = stw[k];                  // e^{-2pi i k/256}
            float Ax = hk.x + hm.x, Ay = hk.y - hm.y;
            float Bx = hk.x - hm.x, By = hk.y + hm.y;
            float cr = c.x * Bx + c.y * By;     // Re(conj(c)*B)
            float ci = c.x * By - c.y * Bx;     // Im(conj(c)*B)
            v[q] = make_float2(Ax - ci, Ay + cr);   // Z = A + i*conj(c)*B
        }
        fft128_core<true>(v, sbuf[f], sbuf[f] + 136, t, stw);
        float2* d = out2 + ((p << 8) + x0 + fc) * 128;
#pragma unroll
        for (int q = 0; q < 4; ++q)
            d[t + 32 * q] = make_float2(v[q].x * s, v[q].y * s);
    }
}

// ---------------------------------------------------------------------------
extern "C" void kernel_launch(void* const* d_in, const int* in_sizes, int n_in,
                              void* d_out, int out_size) {
    const float* x     = (const float*)d_in[0];
    const float* psf   = (const float*)d_in[1];
    const float* alpha = (const float*)d_in[2];
    float* out = (float*)d_out;

    float2 *SA, *SB, *SC;
    cudaGetSymbolAddress((void**)&SA, g_SA);
    cudaGetSymbolAddress((void**)&SB, g_SB);
    cudaGetSymbolAddress((void**)&SC, g_SC);

    k_twinit<<<1, 256>>>();

    // FB^T half (rows 0..128) -> SA
    k_fbrows<<<800, dim3(64, 8)>>>(psf, SC);
    k_fbcol<<<dim3(5, NPLANES), 256>>>(SC, SA);

    // Fx^T[p][u][vh] -> SC  (paired real row FFTs, fused transpose+colFFT)
    k_x128p<<<2048, dim3(32, 8)>>>(x, SB);
    k_xcol<<<dim3(8, NPLANES), dim3(32, 8)>>>(SB, SC);

    // frequency-domain solve -> SB holds FX half (rows 0..128)
    k_mid<<<NPLANES * 128 * 128 / 256, 256>>>(alpha);

    // G half -> SA ; then Hermitian-packed real inverse -> out
    k_half256<<<NPLANES * 129 / 8, dim3(64, 8)>>>(SB, SA);
    k_final<<<dim3(16, NPLANES), dim3(32, 8)>>>(SA, (float2*)out);
}

// round 5
// speedup vs baseline: 2.7001x; 1.0096x over previous
#include <cuda_runtime.h>
#include <math.h>

// Shapes fixed: x (4,64,128,128), k (4,64,25,25), alpha (1,64,1,1), sf=2.
// Output (4,64,256,256) fp32.
#define NPLANES 256
#define NCH 64
#define HSTRIDE (129 * 256)   // half-spectrum plane stride (rows 0..128)

__device__ float2 g_SA[NPLANES * HSTRIDE];     // 67.6 MB : FB half
__device__ float2 g_SB[NPLANES * HSTRIDE];     // 67.6 MB : x row-FFTs, then G half
__device__ float2 g_SC[NPLANES * 128 * 128];   // 33.5 MB : Rf, then Fx^T
__device__ float2 g_tw[256];                   // e^{-2*pi*i t/256}

__global__ void k_twinit() {
    int t = threadIdx.x;
    float s, c;
    sincospif(-(float)t * (1.0f / 128.0f), &s, &c);
    g_tw[t] = make_float2(c, s);
}

#define SP(i) ((i) + ((i) >> 4))

template <bool INV>
__device__ __forceinline__ float2 twmul(float2 a, float2 w) {
    float wy = INV ? -w.y : w.y;
    return make_float2(a.x * w.x - a.y * wy, a.x * wy + a.y * w.x);
}

template <bool INV>
__device__ __forceinline__ void bfly4(float2 v[4]) {
    float2 t0 = make_float2(v[0].x + v[2].x, v[0].y + v[2].y);
    float2 t1 = make_float2(v[0].x - v[2].x, v[0].y - v[2].y);
    float2 t2 = make_float2(v[1].x + v[3].x, v[1].y + v[3].y);
    float2 t3 = make_float2(v[1].x - v[3].x, v[1].y - v[3].y);
    v[0] = make_float2(t0.x + t2.x, t0.y + t2.y);
    v[2] = make_float2(t0.x - t2.x, t0.y - t2.y);
    if (!INV) {
        v[1] = make_float2(t1.x + t3.y, t1.y - t3.x);
        v[3] = make_float2(t1.x - t3.y, t1.y + t3.x);
    } else {
        v[1] = make_float2(t1.x - t3.y, t1.y + t3.x);
        v[3] = make_float2(t1.x + t3.y, t1.y - t3.x);
    }
}

template <bool INV>
__device__ __forceinline__ void fft256_core(float2 v[4], float2* s0, float2* s1,
                                            int t, const float2* tw) {
    bfly4<INV>(v);
    s0[SP(4 * t + 0)] = v[0]; s0[SP(4 * t + 1)] = v[1];
    s0[SP(4 * t + 2)] = v[2]; s0[SP(4 * t + 3)] = v[3];
    __syncthreads();
    {
        int jm = t & 3;
        v[0] = s0[SP(t)];       v[1] = s0[SP(t + 64)];
        v[2] = s0[SP(t + 128)]; v[3] = s0[SP(t + 192)];
        v[1] = twmul<INV>(v[1], tw[16 * jm]);
        v[2] = twmul<INV>(v[2], tw[32 * jm]);
        v[3] = twmul<INV>(v[3], tw[48 * jm]);
        bfly4<INV>(v);
        int d = 4 * (t - jm) + jm;
        s1[SP(d)] = v[0]; s1[SP(d + 4)] = v[1];
        s1[SP(d + 8)] = v[2]; s1[SP(d + 12)] = v[3];
    }
    __syncthreads();
    {
        int jm = t & 15;
        v[0] = s1[SP(t)];       v[1] = s1[SP(t + 64)];
        v[2] = s1[SP(t + 128)]; v[3] = s1[SP(t + 192)];
        v[1] = twmul<INV>(v[1], tw[4 * jm]);
        v[2] = twmul<INV>(v[2], tw[8 * jm]);
        v[3] = twmul<INV>(v[3], tw[12 * jm]);
        bfly4<INV>(v);
        int d = 4 * (t - jm) + jm;
        s0[SP(d)] = v[0]; s0[SP(d + 16)] = v[1];
        s0[SP(d + 32)] = v[2]; s0[SP(d + 48)] = v[3];
    }
    __syncthreads();
    {
        v[0] = s0[SP(t)];       v[1] = s0[SP(t + 64)];
        v[2] = s0[SP(t + 128)]; v[3] = s0[SP(t + 192)];
        v[1] = twmul<INV>(v[1], tw[t]);
        v[2] = twmul<INV>(v[2], tw[2 * t]);
        v[3] = twmul<INV>(v[3], tw[3 * t]);
        bfly4<INV>(v);
    }
}

template <bool INV>
__device__ __forceinline__ void fft128_core(float2 v[4], float2* s0, float2* s1,
                                            int t, const float2* tw) {
    bfly4<INV>(v);
    s0[SP(4 * t + 0)] = v[0]; s0[SP(4 * t + 1)] = v[1];
    s0[SP(4 * t + 2)] = v[2]; s0[SP(4 * t + 3)] = v[3];
    __syncwarp();
    {
        int jm = t & 3;
        v[0] = s0[SP(t)];      v[1] = s0[SP(t + 32)];
        v[2] = s0[SP(t + 64)]; v[3] = s0[SP(t + 96)];
        v[1] = twmul<INV>(v[1], tw[16 * jm]);
        v[2] = twmul<INV>(v[2], tw[32 * jm]);
        v[3] = twmul<INV>(v[3], tw[48 * jm]);
        bfly4<INV>(v);
        int d = 4 * (t - jm) + jm;
        s1[SP(d)] = v[0]; s1[SP(d + 4)] = v[1];
        s1[SP(d + 8)] = v[2]; s1[SP(d + 12)] = v[3];
    }
    __syncwarp();
    {
        int jm = t & 15;
        v[0] = s1[SP(t)];      v[1] = s1[SP(t + 32)];
        v[2] = s1[SP(t + 64)]; v[3] = s1[SP(t + 96)];
        v[1] = twmul<INV>(v[1], tw[4 * jm]);
        v[2] = twmul<INV>(v[2], tw[8 * jm]);
        v[3] = twmul<INV>(v[3], tw[12 * jm]);
        bfly4<INV>(v);
        int d = 4 * (t - jm) + jm;
        s0[SP(d)] = v[0]; s0[SP(d + 16)] = v[1];
        s0[SP(d + 32)] = v[2]; s0[SP(d + 48)] = v[3];
    }
    __syncwarp();
    {
        float2 a0 = s0[SP(t)],      b0 = s0[SP(t + 64)];
        float2 a1 = s0[SP(t + 32)], b1 = s0[SP(t + 96)];
        float2 bw0 = twmul<INV>(b0, tw[2 * t]);
        float2 bw1 = twmul<INV>(b1, tw[2 * (t + 32)]);
        v[0] = make_float2(a0.x + bw0.x, a0.y + bw0.y);
        v[2] = make_float2(a0.x - bw0.x, a0.y - bw0.y);
        v[1] = make_float2(a1.x + bw1.x, a1.y + bw1.y);
        v[3] = make_float2(a1.x - bw1.x, a1.y - bw1.y);
    }
}

__global__ void k_fbrows(const float* __restrict__ psf, float2* __restrict__ Rf) {
    __shared__ float2 sbuf[8][2 * 272];
    __shared__ float2 stw[256];
    int t = threadIdx.x, ry = threadIdx.y;
    int lt = ry * 64 + t;
    if (lt < 256) stw[lt] = g_tw[lt];
    int gr = blockIdx.x * 8 + ry;
    int p = gr / 25, r = gr - p * 25;
    const float* kp = psf + p * 625 + r * 25;
    float2 v[4];
#pragma unroll
    for (int q = 0; q < 4; ++q) {
        int c = (t + 64 * q + 12) & 255;
        v[q] = make_float2(c < 25 ? kp[c] : 0.f, 0.f);
    }
    __syncthreads();
    fft256_core<false>(v, sbuf[ry], sbuf[ry] + 272, t, stw);
    float2* d = Rf + gr * 256;
    d[t] = v[0]; d[t + 64] = v[1]; d[t + 128] = v[2]; d[t + 192] = v[3];
}

__global__ void k_fbcol(const float2* __restrict__ Rf, float2* __restrict__ FBt) {
    __shared__ float2 sRf[25][32];
    __shared__ float2 stw[256];
    int p = blockIdx.y;
    int u0 = blockIdx.x * 32;
    int v = threadIdx.x;
    stw[v] = g_tw[v];
    for (int e = v; e < 800; e += 256) {
        int r = e >> 5, uu = e & 31;
        sRf[r][uu] = Rf[p * 6400 + r * 256 + u0 + uu];
    }
    __syncthreads();

    float2 twr[25];
#pragma unroll
    for (int r = 0; r < 25; ++r)
        twr[r] = stw[(v * (r - 12)) & 255];

#pragma unroll 2
    for (int u = 0; u < 32; ++u) {
        int ug = u0 + u;
        if (ug > 128) break;
        float2 acc = make_float2(0.f, 0.f);
#pragma unroll
        for (int r = 0; r < 25; ++r) {
            float2 a = sRf[r][u];
            acc.x += a.x * twr[r].x - a.y * twr[r].y;
            acc.y += a.x * twr[r].y + a.y * twr[r].x;
        }
        FBt[p * HSTRIDE + ug * 256 + v] = acc;
    }
}

__global__ void k_x128p(const float* __restrict__ x, float2* __restrict__ R1) {
    __shared__ float2 sbuf[8][2 * 136];
    __shared__ float2 stw[256];
    int t = threadIdx.x, ry = threadIdx.y;
    int lt = ry * 32 + t;
    stw[lt] = g_tw[lt];
    int pr = blockIdx.x * 8 + ry;
    const float* xa = x + pr * 256;
    float2 v[4];
#pragma unroll
    for (int q = 0; q < 4; ++q)
        v[q] = make_float2(xa[t + 32 * q], xa[128 + t + 32 * q]);
    __syncthreads();
    fft128_core<false>(v, sbuf[ry], sbuf[ry] + 136, t, stw);
    float2* s0 = sbuf[ry];
#pragma unroll
    for (int q = 0; q < 4; ++q) s0[SP(t + 32 * q)] = v[q];
    __syncwarp();
    float2* da = R1 + pr * 256;
    float2* db = da + 128;
#pragma unroll
    for (int q = 0; q < 4; ++q) {
        int k = t + 32 * q;
        float2 Zk = s0[SP(k)];
        float2 Zm = s0[SP((128 - k) & 127)];
        da[k] = make_float2(0.5f * (Zk.x + Zm.x), 0.5f * (Zk.y - Zm.y));
        db[k] = make_float2(0.5f * (Zk.y + Zm.y), 0.5f * (Zm.x - Zk.x));
    }
}

__global__ void k_xcol(const float2* __restrict__ R1, float2* __restrict__ Fx) {
    __shared__ float2 tile[128][17];
    __shared__ float2 sbuf[8][2 * 136];
    __shared__ float2 stw[256];
    int t = threadIdx.x, f = threadIdx.y;
    int tid = f * 32 + t;
    stw[tid] = g_tw[tid];
    int p = blockIdx.y, u0 = blockIdx.x * 16;
    const float2* Rp = R1 + p * 16384;
#pragma unroll
    for (int it = 0; it < 8; ++it) {
        int idx = it * 256 + tid;
        int y = idx >> 4, ff = idx & 15;
        tile[y][ff] = Rp[y * 128 + u0 + ff];
    }
    __syncthreads();
#pragma unroll
    for (int rep = 0; rep < 2; ++rep) {
        int fc = f + 8 * rep;
        float2 v[4];
#pragma unroll
        for (int q = 0; q < 4; ++q) v[q] = tile[t + 32 * q][fc];
        fft128_core<false>(v, sbuf[f], sbuf[f] + 136, t, stw);
        __syncwarp();
#pragma unroll
        for (int q = 0; q < 4; ++q) tile[t + 32 * q][fc] = v[q];
    }
    __syncthreads();
    float2* Fp = Fx + p * 16384;
#pragma unroll
    for (int it = 0; it < 8; ++it) {
        int idx = it * 256 + tid;
        int r = idx & 127, ff = idx >> 7;
        Fp[(u0 + ff) * 128 + r] = tile[r][ff];
    }
}

__device__ __forceinline__ float2 cmulf(float2 a, float2 b) {
    return make_float2(a.x * b.x - a.y * b.y, a.x * b.y + a.y * b.x);
}

__global__ void k_solve(const float* __restrict__ alpha) {
    __shared__ float2 sbuf[8][2 * 272];
    __shared__ float2 stw[256];
    int t = threadIdx.x, ry = threadIdx.y;     // (64,8)
    int lt = ry * 64 + t;
    if (lt < 256) stw[lt] = g_tw[lt];
    __syncthreads();

    int p = blockIdx.y;
    int A = blockIdx.x * 8 + ry;               // 0..135; rows >128 idle
    int AA = A <= 128 ? A : 128;
    bool hi = (AA == 128);
    int vv = hi ? 0 : AA;

    float a = alpha[p & (NCH - 1)];
    float be = 1.f / (1.f + expf(9.f - a)) + 1e-3f;
    float ibe = 1.f / be;

    const float2* FBp = g_SA + p * HSTRIDE;
    const float2* FBd = FBp + vv * 256;
    const float2* FBm = FBp + (128 - vv) * 256;
    const float2* Fxr = g_SC + (p << 14) + (vv << 7);

    float2 twv0 = stw[vv], twv1 = stw[vv + 128];
    float2 pv0 = make_float2(1.f + twv0.x, twv0.y);
    float2 pv1 = make_float2(1.f + twv1.x, twv1.y);

    float2 v[4];
#pragma unroll
    for (int half = 0; half < 2; ++half) {
        int u = t + 64 * half;
        float2 fx = Fxr[u];

        float2 FB[4];
        FB[0] = FBd[u];
        FB[1] = FBd[u + 128];
        if (vv == 0) {
            FB[2] = FBm[u];
            FB[3] = FBm[u + 128];
        } else {
            float2 t0 = FBm[(256 - u) & 255];
            float2 t1 = FBm[128 - u];
            FB[2] = make_float2(t0.x, -t0.y);
            FB[3] = make_float2(t1.x, -t1.y);
        }

        float2 twu0 = stw[u], twu1 = stw[u + 128];
        float2 pu0 = make_float2(1.f + twu0.x, twu0.y);
        float2 pu1 = make_float2(1.f + twu1.x, twu1.y);

        float2 FR[4];
        float2 sBR = make_float2(0.f, 0.f);
        float sW = 0.f;
#pragma unroll
        for (int q = 0; q < 4; ++q) {
            float2 fb = FB[q];
            float2 P = cmulf((q & 1) ? pu1 : pu0, (q >> 1) ? pv1 : pv0);
            float2 m = make_float2(fb.x + be * P.x, -fb.y + be * P.y);
            float2 fr = cmulf(fx, m);
            FR[q] = fr;
            sBR.x += fb.x * fr.x - fb.y * fr.y;
            sBR.y += fb.x * fr.y + fb.y * fr.x;
            sW += fb.x * fb.x + fb.y * fb.y;
        }
        sBR.x *= 0.25f; sBR.y *= 0.25f; sW *= 0.25f;
        float inv = 1.f / (sW + be);
        float2 iw = make_float2(sBR.x * inv, sBR.y * inv);

        int qlo = hi ? 2 : 0;
#pragma unroll
        for (int j = 0; j < 2; ++j) {
            int q = qlo + j;
            float2 tmp = make_float2(FB[q].x * iw.x + FB[q].y * iw.y,
                                     FB[q].x * iw.y - FB[q].y * iw.x);
            float2 Q = make_float2((FR[q].x - tmp.x) * ibe,
                                   (FR[q].y - tmp.y) * ibe);
            v[half + 2 * j] = Q;
        }
    }

    fft256_core<true>(v, sbuf[ry], sbuf[ry] + 272, t, stw);

    if (A <= 128) {
        float2* d = g_SB + p * HSTRIDE + A * 256;
        d[t] = v[0]; d[t + 64] = v[1]; d[t + 128] = v[2]; d[t + 192] = v[3];
    }
}

__global__ void k_final(const float2* __restrict__ G, float2* __restrict__ out2) {
    __shared__ float2 tile[129][17];
    __shared__ float2 sbuf[8][2 * 136];
    __shared__ float2 stw[256];
    int t = threadIdx.x, f = threadIdx.y;
    int tid = f * 32 + t;
    stw[tid] = g_tw[tid];
    int p = blockIdx.y, x0 = blockIdx.x * 16;
    const float2* Gp = G + p * HSTRIDE;
#pragma unroll
    for (int it = 0; it < 9; ++it) {
        int idx = it * 256 + tid;
        int A = idx >> 4, ff = idx & 15;
        if (A < 129) tile[A][ff] = Gp[A * 256 + x0 + ff];
    }
    __syncthreads();
    const float s = 1.0f / 65536.0f;
#pragma unroll
    for (int rep = 0; rep < 2; ++rep) {
        int fc = f + 8 * rep;
        float2 v[4];
#pragma unroll
        for (int q = 0; q < 4; ++q) {
            int k = t + 32 * q;
            float2 hk = tile[k][fc];
            float2 hm = tile[128 - k][fc];
            float2 c = stw[k];
            float Ax = hk.x + hm.x, Ay = hk.y - hm.y;
            float Bx = hk.x - hm.x, By = hk.y + hm.y;
            float cr = c.x * Bx + c.y * By;
            float ci = c.x * By - c.y * Bx;
            v[q] = make_float2(Ax - ci, Ay + cr);
        }
        fft128_core<true>(v, sbuf[f], sbuf[f] + 136, t, stw);
        float2* d = out2 + ((p << 8) + x0 + fc) * 128;
#pragma unroll
        for (int q = 0; q < 4; ++q)
            d[t + 32 * q] = make_float2(v[q].x * s, v[q].y * s);
    }
}

extern "C" void kernel_launch(void* const* d_in, const int* in_sizes, int n_in,
                              void* d_out, int out_size) {
    const float* x     = (const float*)d_in[0];
    const float* psf   = (const float*)d_in[1];
    const float* alpha = (const float*)d_in[2];
    float* out = (float*)d_out;

    float2 *SA, *SB, *SC;
    cudaGetSymbolAddress((void**)&SA, g_SA);
    cudaGetSymbolAddress((void**)&SB, g_SB);
    cudaGetSymbolAddress((void**)&SC, g_SC);

    k_twinit<<<1, 256>>>();

    // FB^T half (rows 0..128) -> SA
    k_fbrows<<<800, dim3(64, 8)>>>(psf, SC);
    k_fbcol<<<dim3(5, NPLANES), 256>>>(SC, SA);

    // Fx^T[p][u][vh] -> SC
    k_x128p<<<2048, dim3(32, 8)>>>(x, SB);
    k_xcol<<<dim3(8, NPLANES), dim3(32, 8)>>>(SB, SC);

    // FUSED solve + inverse-256 -> SB holds G half (rows 0..128)
    k_solve<<<dim3(17, NPLANES), dim3(64, 8)>>>(alpha);

    // Hermitian-packed real inverse along width -> out
    k_final<<<dim3(16, NPLANES), dim3(32, 8)>>>(SB, (float2*)out);
}